// round 15
// baseline (speedup 1.0000x reference)
#include <cuda_runtime.h>
#include <cuda_fp16.h>
#include <math.h>
#include <stdint.h>

typedef unsigned long long ull;

// ---------------- problem constants ----------------
#define T_DIM 64
#define B_DIM 32
#define C_DIM 256
#define V_DIM 25
#define H_DIM 8
#define HD_DIM 32
#define PLANE  (B_DIM * C_DIM * V_DIM)    // 204800
#define TOT    (T_DIM * PLANE)            // 13107200
#define NF     (T_DIM * B_DIM * V_DIM)    // 51200  (GEMM N)
#define BWORDS ((size_t)16 * NF * 8)      // 6,553,600 words per B plane

// ---------------- device scratch ----------------
__device__ __align__(16) float g_yq[TOT];    // q bn-conv out; later proj bn-conv out
__device__ __align__(16) float g_yk[TOT];
__device__ __align__(16) float g_yv[TOT];
__device__ unsigned char g_qs8[TOT];         // q spikes (0/1)
__device__ unsigned char g_kvl8[TOT];        // k_s * v_s (0/1)

// pre-packed weight fragments: [k16 0..15][mf 0..15][lane 0..31][w 0..3]
__device__ __align__(16) uint32_t g_wpkhi[4][32768];
__device__ __align__(16) uint32_t g_wpklo[4][32768];

// pre-packed B fragment planes: word ((K*NF + n)*8 + c2*2 + w) packs
// k = (16K + 8w + 2*c2, +1) at column n, as f16x2. hi/lo split planes.
__device__ __align__(16) uint32_t g_bxhi[BWORDS];
__device__ __align__(16) uint32_t g_bxlo[BWORDS];
__device__ __align__(16) uint32_t g_bqhi[BWORDS];   // qkv_in; later attn
__device__ __align__(16) uint32_t g_bqlo[BWORDS];

__device__ float g_scale[4][C_DIM];
__device__ float g_shift[4][C_DIM];
__device__ float g_topo[H_DIM][V_DIM * V_DIM];
__device__ float g_decay[C_DIM];

// ---------------- helpers ----------------
#define LO_SCALE 1024.0f
#define LO_INV   (1.0f / 1024.0f)

__device__ __forceinline__ void split_h2(float a, float b, uint32_t& h, uint32_t& l) {
    __half ha = __float2half_rn(a), hb = __float2half_rn(b);
    float ra = (a - __half2float(ha)) * LO_SCALE;
    float rb = (b - __half2float(hb)) * LO_SCALE;
    __half la = __float2half_rn(ra), lb = __float2half_rn(rb);
    __half2 hh = __halves2half2(ha, hb), ll = __halves2half2(la, lb);
    h = *reinterpret_cast<uint32_t*>(&hh);
    l = *reinterpret_cast<uint32_t*>(&ll);
}

__device__ __forceinline__ void mma16(float* c, const uint32_t* a, const uint32_t* b) {
    asm volatile(
        "mma.sync.aligned.m16n8k16.row.col.f32.f16.f16.f32 "
        "{%0,%1,%2,%3}, {%4,%5,%6,%7}, {%8,%9}, {%0,%1,%2,%3};"
        : "+f"(c[0]), "+f"(c[1]), "+f"(c[2]), "+f"(c[3])
        : "r"(a[0]), "r"(a[1]), "r"(a[2]), "r"(a[3]), "r"(b[0]), "r"(b[1]));
}

// ---------------- K0: prep ----------------
struct PrepArgs {
    const float* w[4];
    const float* gamma[4];
    const float* beta[4];
    const float* mean[4];
    const float* var[4];
    const float* projb;
    const float* base;
    const float* learned;
    const float* sdw;
};

__global__ void k_prep(PrepArgs p) {
    int blk = blockIdx.x, tid = threadIdx.x;
    if (blk < 4) {
        const float* w = p.w[blk];
        for (int idx = tid; idx < 32768; idx += 256) {
            int k16 = idx >> 11;
            int rest = idx & 2047;
            int mf = rest >> 7;
            int r2 = rest & 127;
            int lane = r2 >> 2;
            int wq = r2 & 3;
            int g = lane >> 2, c = lane & 3;
            int row = mf * 16 + g + (wq & 1) * 8;
            int col = k16 * 16 + 2 * c + ((wq & 2) ? 8 : 0);
            uint32_t hi, lo;
            split_h2(w[row * C_DIM + col], w[row * C_DIM + col + 1], hi, lo);
            g_wpkhi[blk][idx] = hi;
            g_wpklo[blk][idx] = lo;
        }
        float sc = p.gamma[blk][tid] * rsqrtf(p.var[blk][tid] + 1e-5f);
        float sh = p.beta[blk][tid] - p.mean[blk][tid] * sc;
        if (blk == 3) sh += p.projb[tid] * sc;
        g_scale[blk][tid] = sc;
        g_shift[blk][tid] = sh;
    } else if (blk == 4) {
        if (tid < H_DIM * V_DIM) {
            int h = tid / V_DIM, i = tid - h * V_DIM;
            float l[V_DIM];
            float mx = -1e30f;
            for (int j = 0; j < V_DIM; j++) {
                l[j] = p.base[i * V_DIM + j] + 0.5f * p.learned[(h * V_DIM + i) * V_DIM + j];
                mx = fmaxf(mx, l[j]);
            }
            float sum = 0.f;
            for (int j = 0; j < V_DIM; j++) { l[j] = expf(l[j] - mx); sum += l[j]; }
            float inv = 1.f / sum;
            for (int j = 0; j < V_DIM; j++) g_topo[h][i * V_DIM + j] = l[j] * inv;
        }
    } else {
        float w = p.sdw[tid];
        float sg = 1.f / (1.f + expf(-w));
        g_decay[tid] = fminf(0.99f, fmaxf(0.01f, sg));
    }
}

// ---------------- K1: transpose + split-pack x and qkv_in ----------------
__global__ void k_trans(const float* __restrict__ x, const float* __restrict__ alpha) {
    extern __shared__ float dynsm[];
    float* sxf = dynsm;
    float* sqf = dynsm + C_DIM * V_DIM;
    __shared__ float alp[C_DIM];
    int tid = threadIdx.x;
    alp[tid] = alpha[tid];
    __syncthreads();

    int t = blockIdx.x >> 5;
    int b = blockIdx.x & 31;
    const float* xin = x + (size_t)t * PLANE + b * (C_DIM * V_DIM);
    const float* xpr = xin - PLANE;
    int nbase = t * 800 + b * V_DIM;

    for (int idx = tid; idx < C_DIM * V_DIM; idx += 256) {
        int c = idx / V_DIM;
        float xv = xin[idx];
        float g = (t == 0) ? 0.f : fabsf(xv - xpr[idx]);
        float a = alp[c];
        sxf[idx] = xv;
        sqf[idx] = a * g + (1.f - a) * xv;
    }
    __syncthreads();

    for (int widx = tid; widx < V_DIM * 128; widx += 256) {
        int v = widx >> 7, j = widx & 127;
        int base = 2 * j * V_DIM + v;
        int K = j >> 3;
        int c2w = ((j & 3) << 1) | ((j >> 2) & 1);
        size_t addr = ((size_t)K * NF + (nbase + v)) * 8 + c2w;
        uint32_t h, l;
        split_h2(sxf[base], sxf[base + V_DIM], h, l);
        g_bxhi[addr] = h; g_bxlo[addr] = l;
        split_h2(sqf[base], sqf[base + V_DIM], h, l);
        g_bqhi[addr] = h; g_bqlo[addr] = l;
    }
}

// ---------------- K2/K5: fp16x3 mma.sync GEMM + fused BN ----------------
// Block tile 256x64, BK=32, 512 threads (16 warps), warp tile 64x16, 1 CTA/SM.
// Full M per CTA: B plane read once per pass.
#define BM 256
#define BN 64
#define BK 32
#define GTHREADS 512
// u32 word offsets inside one buffer (10240 words = 40 KB)
#define AH_OFF 0
#define AL_OFF 4096
#define BH_OFF 8192
#define BL_OFF 9216
#define BUF_WORDS 10240
#define GSMEM_BYTES (2 * BUF_WORDS * 4)

__device__ __forceinline__ void stage_load(const uint32_t* __restrict__ Ahi, const uint32_t* __restrict__ Alo,
                                           const uint32_t* __restrict__ Bhi, const uint32_t* __restrict__ Blo,
                                           size_t bfrag, int kc, int tid,
                                           uint4* ah4, uint4* al4, uint2* bh2, uint2* bl2) {
#pragma unroll
    for (int kf = 0; kf < 2; kf++) {
        // A: all 16 mf fragments; thread -> (mf = tid>>5, lane = tid&31)
        size_t abase = ((size_t)((kc * 2 + kf) * 16 + (tid >> 5)) << 7) + (tid & 31) * 4;
        ah4[kf] = *reinterpret_cast<const uint4*>(Ahi + abase);
        al4[kf] = *reinterpret_cast<const uint4*>(Alo + abase);
        if (tid < 256) {
            size_t baddr = (size_t)(kc * 2 + kf) * (NF * 8) + bfrag;
            bh2[kf] = *reinterpret_cast<const uint2*>(Bhi + baddr);
            bl2[kf] = *reinterpret_cast<const uint2*>(Blo + baddr);
        }
    }
}

__device__ __forceinline__ void stage_store(uint32_t* sb, int tid,
                                            const uint4* ah4, const uint4* al4,
                                            const uint2* bh2, const uint2* bl2) {
#pragma unroll
    for (int kf = 0; kf < 2; kf++) {
        *reinterpret_cast<uint4*>(sb + AH_OFF + kf * 2048 + tid * 4) = ah4[kf];
        *reinterpret_cast<uint4*>(sb + AL_OFF + kf * 2048 + tid * 4) = al4[kf];
        if (tid < 256) {
            *reinterpret_cast<uint2*>(sb + BH_OFF + kf * 512 + tid * 2) = bh2[kf];
            *reinterpret_cast<uint2*>(sb + BL_OFF + kf * 512 + tid * 2) = bl2[kf];
        }
    }
}

__global__ void __launch_bounds__(GTHREADS, 1) k_gemm_mma(int pass) {
    extern __shared__ uint32_t sm32[];
    int mt;
    const uint32_t* Bhi;
    const uint32_t* Blo;
    float* out;
    if (pass == 0) {
        mt = blockIdx.z;
        if (mt == 2) { Bhi = g_bxhi; Blo = g_bxlo; }
        else         { Bhi = g_bqhi; Blo = g_bqlo; }
        out = (mt == 0) ? g_yq : (mt == 1) ? g_yk : g_yv;
    } else {
        mt = 3;
        Bhi = g_bqhi; Blo = g_bqlo;
        out = g_yq;
    }
    const uint32_t* Ahi = g_wpkhi[mt];
    const uint32_t* Alo = g_wpklo[mt];
    int n0 = blockIdx.x * BN;
    int tid = threadIdx.x;
    int lane = tid & 31, wid = tid >> 5;
    int wm = wid >> 2;   // 0..3 -> 64-row group
    int wn = wid & 3;    // 0..3 -> 16-col group

    // per-thread B fragment offset within one K-plane (threads 0..255)
    size_t bfrag = 0;
    if (tid < 256) {
        int nf = tid >> 5, g2 = (tid & 31) >> 2, cc = tid & 3;
        bfrag = (size_t)(n0 + nf * 8 + g2) * 8 + cc * 2;
    }

    float acc1[4][2][4], acc2[4][2][4];
#pragma unroll
    for (int i = 0; i < 4; i++)
#pragma unroll
        for (int j = 0; j < 2; j++)
#pragma unroll
            for (int r = 0; r < 4; r++) { acc1[i][j][r] = 0.f; acc2[i][j][r] = 0.f; }

    uint4 ah4[2], al4[2];
    uint2 bh2[2], bl2[2];
    stage_load(Ahi, Alo, Bhi, Blo, bfrag, 0, tid, ah4, al4, bh2, bl2);
    stage_store(sm32, tid, ah4, al4, bh2, bl2);
    __syncthreads();

    for (int kc = 0; kc < C_DIM / BK; kc++) {
        uint32_t* sb = sm32 + (kc & 1) * BUF_WORDS;
        bool more = (kc + 1 < C_DIM / BK);
        if (more) stage_load(Ahi, Alo, Bhi, Blo, bfrag, kc + 1, tid, ah4, al4, bh2, bl2);

#pragma unroll
        for (int kf = 0; kf < 2; kf++) {
            uint32_t Bh[2][2], Bl[2][2];
#pragma unroll
            for (int j = 0; j < 2; j++) {
                int fi = kf * 512 + ((wn * 2 + j) * 32 + lane) * 2;
                uint2 bh = *reinterpret_cast<const uint2*>(sb + BH_OFF + fi);
                uint2 bl = *reinterpret_cast<const uint2*>(sb + BL_OFF + fi);
                Bh[j][0] = bh.x; Bh[j][1] = bh.y;
                Bl[j][0] = bl.x; Bl[j][1] = bl.y;
            }
#pragma unroll
            for (int i = 0; i < 4; i++) {
                int fi = kf * 2048 + ((wm * 4 + i) * 32 + lane) * 4;
                uint4 a4 = *reinterpret_cast<const uint4*>(sb + AH_OFF + fi);
                uint4 l4 = *reinterpret_cast<const uint4*>(sb + AL_OFF + fi);
                uint32_t Ah[4] = {a4.x, a4.y, a4.z, a4.w};
                uint32_t Al[4] = {l4.x, l4.y, l4.z, l4.w};
#pragma unroll
                for (int j = 0; j < 2; j++) {
                    mma16(acc1[i][j], Ah, Bh[j]);
                    mma16(acc2[i][j], Ah, Bl[j]);
                    mma16(acc2[i][j], Al, Bh[j]);
                }
            }
        }
        if (more) stage_store(sm32 + ((kc + 1) & 1) * BUF_WORDS, tid, ah4, al4, bh2, bl2);
        __syncthreads();
    }

    int g = lane >> 2, c = lane & 3;
#pragma unroll
    for (int i = 0; i < 4; i++) {
        int r0 = wm * 64 + i * 16 + g;
        int r1 = r0 + 8;
        float sc0 = g_scale[mt][r0], sh0 = g_shift[mt][r0];
        float sc1 = g_scale[mt][r1], sh1 = g_shift[mt][r1];
#pragma unroll
        for (int j = 0; j < 2; j++) {
            int ncol = n0 + (wn * 2 + j) * 8 + c * 2;
            float v0 = acc1[i][j][0] + acc2[i][j][0] * LO_INV;
            float v1 = acc1[i][j][1] + acc2[i][j][1] * LO_INV;
            float v2 = acc1[i][j][2] + acc2[i][j][2] * LO_INV;
            float v3 = acc1[i][j][3] + acc2[i][j][3] * LO_INV;
            *reinterpret_cast<float2*>(out + (size_t)r0 * NF + ncol) =
                make_float2(v0 * sc0 + sh0, v1 * sc0 + sh0);
            *reinterpret_cast<float2*>(out + (size_t)r1 * NF + ncol) =
                make_float2(v2 * sc1 + sh1, v3 * sc1 + sh1);
        }
    }
}

// ---------------- K3: triple LIF + kv_local (u8 spikes) ----------------
__global__ void k_lif3() {
    int e = blockIdx.x * 256 + threadIdx.x;
    if (e >= PLANE) return;
    int c = e / 800;
    int nb = e - c * 800;
    int bse = c * NF + nb;
    float vq = 0.f, vk = 0.f, vv = 0.f;
    for (int t = 0; t < T_DIM; t++) {
        int off = bse + t * 800;
        float aq = __ldcs(g_yq + off);
        float ak = __ldcs(g_yk + off);
        float av = __ldcs(g_yv + off);
        float q = vq + (aq - vq) * 0.5f;
        float sq = (q >= 1.f) ? 1.f : 0.f;
        vq = q * (1.f - sq);
        float k = vk + (ak - vk) * 0.5f;
        float sk = (k >= 1.f) ? 1.f : 0.f;
        vk = k * (1.f - sk);
        float v = vv + (av - vv) * 0.5f;
        float sv = (v >= 1.f) ? 1.f : 0.f;
        vv = v * (1.f - sv);
        g_qs8[off] = (unsigned char)sq;
        g_kvl8[off] = (unsigned char)(sk * sv);
    }
}

// ---------------- K4: topo routing + LIF(0.5) + SSRE -> packed attn ----------------
__global__ void __launch_bounds__(224) k_topo_ssre() {
    int bid = blockIdx.x;
    int b = bid >> 5;
    int rest = bid & 31;
    int h = rest >> 2;
    int dg = rest & 3;
    int tid = threadIdx.x;

    __shared__ float topo_s[V_DIM * V_DIM];
    __shared__ float kvb[2][200];
    __shared__ float satt[200];
    for (int i = tid; i < V_DIM * V_DIM; i += 224) topo_s[i] = g_topo[h][i];

    bool active = tid < 200;
    int d_local = tid / V_DIM;
    int i = tid - d_local * V_DIM;
    int c = h * HD_DIM + dg * 8 + d_local;
    int pbase = c * NF + b * V_DIM + i;
    int cb = h * HD_DIM + dg * 8;

    bool packer = tid < 100;
    int pp = 0, pi = 0;
    size_t paddr_base = 0;
    if (packer) {
        int p = tid / V_DIM;
        pi = tid - p * V_DIM;
        int pj = (cb >> 1) + p;
        int K = pj >> 3;
        int c2w = ((pj & 3) << 1) | ((pj >> 2) & 1);
        paddr_base = ((size_t)K * NF + b * V_DIM + pi) * 8 + c2w;
        pp = p;
    }

    float dec = 0.f;
    if (active) dec = g_decay[h * HD_DIM + dg * 8 + d_local];
    float omd = 1.f - dec;
    float vm = 0.f, S = 0.f;

    if (active) kvb[0][tid] = (float)g_kvl8[pbase];

    for (int t = 0; t < T_DIM; t++) {
        __syncthreads();
        int cur = t & 1;
        if (t + 1 < T_DIM && active) kvb[cur ^ 1][tid] = (float)g_kvl8[pbase + (t + 1) * 800];
        if (active) {
            const float* kr = &kvb[cur][d_local * V_DIM];
            const float* tr = &topo_s[i * V_DIM];
            float sp = 0.f, sp2 = 0.f;
#pragma unroll
            for (int j = 0; j < 24; j += 2) {
                sp += tr[j] * kr[j];
                sp2 += tr[j + 1] * kr[j + 1];
            }
            sp += tr[24] * kr[24] + sp2;
            vm = vm + (sp - vm) * 0.5f;
            float sk = (vm >= 0.5f) ? 1.f : 0.f;
            vm *= (1.f - sk);
            S = dec * S + omd * sk;
            satt[tid] = g_qs8[pbase + t * 800] ? S : 0.f;
        }
        __syncthreads();
        if (packer) {
            float f0 = satt[(2 * pp) * V_DIM + pi];
            float f1 = satt[(2 * pp + 1) * V_DIM + pi];
            uint32_t hw, lw;
            split_h2(f0, f1, hw, lw);
            size_t addr = paddr_base + (size_t)t * (800 * 8);
            g_bqhi[addr] = hw;
            g_bqlo[addr] = lw;
        }
    }
}

// ---------------- K6: final LIF(0.5) + identity ----------------
__global__ void k_final(const float* __restrict__ x, float* __restrict__ out) {
    int e = blockIdx.x * 256 + threadIdx.x;
    if (e >= PLANE) return;
    int c = e / 800;
    int nb = e - c * 800;
    int b = nb / V_DIM;
    int v = nb - b * V_DIM;
    int ybase = c * NF + nb;
    int xoff = b * (C_DIM * V_DIM) + c * V_DIM + v;
    float vm = 0.f;
    for (int t = 0; t < T_DIM; t++) {
        float y = __ldcs(g_yq + ybase + t * 800);
        float vv = vm + (y - vm) * 0.5f;
        float s = (vv >= 0.5f) ? 1.f : 0.f;
        vm = vv * (1.f - s);
        int xo = t * PLANE + xoff;
        out[xo] = s + x[xo];
    }
}

// ---------------- launch ----------------
extern "C" void kernel_launch(void* const* d_in, const int* in_sizes, int n_in,
                              void* d_out, int out_size) {
    const float* x = (const float*)d_in[0];
    const float* alpha = (const float*)d_in[1];

    PrepArgs p;
    p.w[0] = (const float*)d_in[2];
    p.w[1] = (const float*)d_in[3];
    p.w[2] = (const float*)d_in[4];

    if (in_sizes[5] == 625) {
        p.base    = (const float*)d_in[5];
        p.learned = (const float*)d_in[6];
        p.sdw     = (const float*)d_in[7];
        p.w[3]    = (const float*)d_in[8];
        p.projb   = (const float*)d_in[9];
        for (int m = 0; m < 4; m++) {
            int o = 10 + m * 4;
            p.gamma[m] = (const float*)d_in[o + 0];
            p.beta[m]  = (const float*)d_in[o + 1];
            p.mean[m]  = (const float*)d_in[o + 2];
            p.var[m]   = (const float*)d_in[o + 3];
        }
    } else {
        for (int m = 0; m < 3; m++) {
            int o = 5 + m * 4;
            p.gamma[m] = (const float*)d_in[o + 0];
            p.beta[m]  = (const float*)d_in[o + 1];
            p.mean[m]  = (const float*)d_in[o + 2];
            p.var[m]   = (const float*)d_in[o + 3];
        }
        p.base    = (const float*)d_in[17];
        p.learned = (const float*)d_in[18];
        p.sdw     = (const float*)d_in[19];
        p.w[3]    = (const float*)d_in[20];
        p.projb   = (const float*)d_in[21];
        p.gamma[3] = (const float*)d_in[22];
        p.beta[3]  = (const float*)d_in[23];
        p.mean[3]  = (const float*)d_in[24];
        p.var[3]   = (const float*)d_in[25];
    }

    float* out = (float*)d_out;

    cudaFuncSetAttribute(k_gemm_mma, cudaFuncAttributeMaxDynamicSharedMemorySize, GSMEM_BYTES);
    int tsm = 2 * C_DIM * V_DIM * 4;   // 51200 B
    cudaFuncSetAttribute(k_trans, cudaFuncAttributeMaxDynamicSharedMemorySize, tsm);

    k_prep<<<6, 256>>>(p);
    k_trans<<<T_DIM * B_DIM, 256, tsm>>>(x, alpha);
    k_gemm_mma<<<dim3(NF / BN, 1, 3), GTHREADS, GSMEM_BYTES>>>(0);
    k_lif3<<<(PLANE + 255) / 256, 256>>>();
    k_topo_ssre<<<B_DIM * H_DIM * 4, 224>>>();
    k_gemm_mma<<<dim3(NF / BN, 1, 1), GTHREADS, GSMEM_BYTES>>>(1);
    k_final<<<(PLANE + 255) / 256, 256>>>(x, out);
}

// round 16
// speedup vs baseline: 1.0501x; 1.0501x over previous
#include <cuda_runtime.h>
#include <cuda_fp16.h>
#include <math.h>
#include <stdint.h>

typedef unsigned long long ull;

// ---------------- problem constants ----------------
#define T_DIM 64
#define B_DIM 32
#define C_DIM 256
#define V_DIM 25
#define H_DIM 8
#define HD_DIM 32
#define PLANE  (B_DIM * C_DIM * V_DIM)    // 204800
#define TOT    (T_DIM * PLANE)            // 13107200
#define NF     (T_DIM * B_DIM * V_DIM)    // 51200  (GEMM N)
#define BWORDS ((size_t)16 * NF * 8)      // words per B plane

// ---------------- device scratch ----------------
__device__ __align__(16) float g_yq[TOT];    // q bn-conv out; later proj bn-conv out
__device__ __align__(16) float g_yk[TOT];
__device__ __align__(16) float g_yv[TOT];
__device__ unsigned char g_qs8[TOT];         // q spikes (0/1)
__device__ unsigned char g_kvl8[TOT];        // k_s * v_s (0/1)

// pre-packed weight fragments: [k16 0..15][mf 0..15][lane 0..31][w 0..3]
__device__ __align__(16) uint32_t g_wpkhi[4][32768];
__device__ __align__(16) uint32_t g_wpklo[4][32768];

// pre-packed B fragment planes
__device__ __align__(16) uint32_t g_bxhi[BWORDS];
__device__ __align__(16) uint32_t g_bxlo[BWORDS];
__device__ __align__(16) uint32_t g_bqhi[BWORDS];   // qkv_in; later attn
__device__ __align__(16) uint32_t g_bqlo[BWORDS];

__device__ float g_scale[4][C_DIM];
__device__ float g_shift[4][C_DIM];
__device__ float g_topo[H_DIM][V_DIM * V_DIM];
__device__ float g_decay[C_DIM];

// ---------------- helpers ----------------
#define LO_SCALE 1024.0f
#define LO_INV   (1.0f / 1024.0f)

__device__ __forceinline__ void split_h2(float a, float b, uint32_t& h, uint32_t& l) {
    __half ha = __float2half_rn(a), hb = __float2half_rn(b);
    float ra = (a - __half2float(ha)) * LO_SCALE;
    float rb = (b - __half2float(hb)) * LO_SCALE;
    __half la = __float2half_rn(ra), lb = __float2half_rn(rb);
    __half2 hh = __halves2half2(ha, hb), ll = __halves2half2(la, lb);
    h = *reinterpret_cast<uint32_t*>(&hh);
    l = *reinterpret_cast<uint32_t*>(&ll);
}

__device__ __forceinline__ void mma16(float* c, const uint32_t* a, const uint32_t* b) {
    asm volatile(
        "mma.sync.aligned.m16n8k16.row.col.f32.f16.f16.f32 "
        "{%0,%1,%2,%3}, {%4,%5,%6,%7}, {%8,%9}, {%0,%1,%2,%3};"
        : "+f"(c[0]), "+f"(c[1]), "+f"(c[2]), "+f"(c[3])
        : "r"(a[0]), "r"(a[1]), "r"(a[2]), "r"(a[3]), "r"(b[0]), "r"(b[1]));
}

__device__ __forceinline__ void cp16(uint32_t saddr, const void* g) {
    asm volatile("cp.async.ca.shared.global [%0], [%1], 16;" :: "r"(saddr), "l"(g) : "memory");
}
__device__ __forceinline__ void cp8(uint32_t saddr, const void* g) {
    asm volatile("cp.async.ca.shared.global [%0], [%1], 8;" :: "r"(saddr), "l"(g) : "memory");
}
#define CP_COMMIT() asm volatile("cp.async.commit_group;" ::: "memory")
#define CP_WAIT0()  asm volatile("cp.async.wait_group 0;" ::: "memory")

// ---------------- K0: prep ----------------
struct PrepArgs {
    const float* w[4];
    const float* gamma[4];
    const float* beta[4];
    const float* mean[4];
    const float* var[4];
    const float* projb;
    const float* base;
    const float* learned;
    const float* sdw;
};

__global__ void k_prep(PrepArgs p) {
    int blk = blockIdx.x, tid = threadIdx.x;
    if (blk < 4) {
        const float* w = p.w[blk];
        for (int idx = tid; idx < 32768; idx += 256) {
            int k16 = idx >> 11;
            int rest = idx & 2047;
            int mf = rest >> 7;
            int r2 = rest & 127;
            int lane = r2 >> 2;
            int wq = r2 & 3;
            int g = lane >> 2, c = lane & 3;
            int row = mf * 16 + g + (wq & 1) * 8;
            int col = k16 * 16 + 2 * c + ((wq & 2) ? 8 : 0);
            uint32_t hi, lo;
            split_h2(w[row * C_DIM + col], w[row * C_DIM + col + 1], hi, lo);
            g_wpkhi[blk][idx] = hi;
            g_wpklo[blk][idx] = lo;
        }
        float sc = p.gamma[blk][tid] * rsqrtf(p.var[blk][tid] + 1e-5f);
        float sh = p.beta[blk][tid] - p.mean[blk][tid] * sc;
        if (blk == 3) sh += p.projb[tid] * sc;
        g_scale[blk][tid] = sc;
        g_shift[blk][tid] = sh;
    } else if (blk == 4) {
        if (tid < H_DIM * V_DIM) {
            int h = tid / V_DIM, i = tid - h * V_DIM;
            float l[V_DIM];
            float mx = -1e30f;
            for (int j = 0; j < V_DIM; j++) {
                l[j] = p.base[i * V_DIM + j] + 0.5f * p.learned[(h * V_DIM + i) * V_DIM + j];
                mx = fmaxf(mx, l[j]);
            }
            float sum = 0.f;
            for (int j = 0; j < V_DIM; j++) { l[j] = expf(l[j] - mx); sum += l[j]; }
            float inv = 1.f / sum;
            for (int j = 0; j < V_DIM; j++) g_topo[h][i * V_DIM + j] = l[j] * inv;
        }
    } else {
        float w = p.sdw[tid];
        float sg = 1.f / (1.f + expf(-w));
        g_decay[tid] = fminf(0.99f, fmaxf(0.01f, sg));
    }
}

// ---------------- K1: transpose + split-pack x and qkv_in ----------------
__global__ void k_trans(const float* __restrict__ x, const float* __restrict__ alpha) {
    extern __shared__ float dynsm[];
    float* sxf = dynsm;
    float* sqf = dynsm + C_DIM * V_DIM;
    __shared__ float alp[C_DIM];
    int tid = threadIdx.x;
    alp[tid] = alpha[tid];
    __syncthreads();

    int t = blockIdx.x >> 5;
    int b = blockIdx.x & 31;
    const float* xin = x + (size_t)t * PLANE + b * (C_DIM * V_DIM);
    const float* xpr = xin - PLANE;
    int nbase = t * 800 + b * V_DIM;

    for (int idx = tid; idx < C_DIM * V_DIM; idx += 256) {
        int c = idx / V_DIM;
        float xv = xin[idx];
        float g = (t == 0) ? 0.f : fabsf(xv - xpr[idx]);
        float a = alp[c];
        sxf[idx] = xv;
        sqf[idx] = a * g + (1.f - a) * xv;
    }
    __syncthreads();

    for (int widx = tid; widx < V_DIM * 128; widx += 256) {
        int v = widx >> 7, j = widx & 127;
        int base = 2 * j * V_DIM + v;
        int K = j >> 3;
        int c2w = ((j & 3) << 1) | ((j >> 2) & 1);
        size_t addr = ((size_t)K * NF + (nbase + v)) * 8 + c2w;
        uint32_t h, l;
        split_h2(sxf[base], sxf[base + V_DIM], h, l);
        g_bxhi[addr] = h; g_bxlo[addr] = l;
        split_h2(sqf[base], sqf[base + V_DIM], h, l);
        g_bqhi[addr] = h; g_bqlo[addr] = l;
    }
}

// ---------------- K2/K5: fp16x3 mma.sync GEMM + fused BN (cp.async staging) ----------------
// Block tile 128x64, BK=32, 256 threads (8 warps), warp tile 64x16, 2 CTA/SM.
#define BM 128
#define BN 64
#define BK 32
#define GTHREADS 256
#define AH_OFF 0
#define AL_OFF 2048
#define BH_OFF 4096
#define BL_OFF 5120
#define BUF_WORDS 6144
#define GSMEM_BYTES (2 * BUF_WORDS * 4)

// issue async copies for one chunk into buffer at smem word-base smb
__device__ __forceinline__ void stage_cp(uint32_t smb,
                                         const uint32_t* __restrict__ Ahi, const uint32_t* __restrict__ Alo,
                                         const uint32_t* __restrict__ Bhi, const uint32_t* __restrict__ Blo,
                                         size_t bfrag, int kc, int yoff, int tid) {
#pragma unroll
    for (int kf = 0; kf < 2; kf++) {
        size_t abase = ((size_t)((kc * 2 + kf) * 16 + yoff + (tid >> 5)) << 7) + (tid & 31) * 4;
        cp16(smb + (AH_OFF + kf * 1024 + tid * 4) * 4, Ahi + abase);
        cp16(smb + (AL_OFF + kf * 1024 + tid * 4) * 4, Alo + abase);
        size_t baddr = (size_t)(kc * 2 + kf) * (NF * 8) + bfrag;
        cp8(smb + (BH_OFF + kf * 512 + tid * 2) * 4, Bhi + baddr);
        cp8(smb + (BL_OFF + kf * 512 + tid * 2) * 4, Blo + baddr);
    }
}

__global__ void __launch_bounds__(GTHREADS, 2) k_gemm_mma(int pass) {
    extern __shared__ uint32_t sm32[];
    uint32_t smb = (uint32_t)__cvta_generic_to_shared(sm32);
    int mt;
    const uint32_t* Bhi;
    const uint32_t* Blo;
    float* out;
    if (pass == 0) {
        mt = blockIdx.z;
        if (mt == 2) { Bhi = g_bxhi; Blo = g_bxlo; }
        else         { Bhi = g_bqhi; Blo = g_bqlo; }
        out = (mt == 0) ? g_yq : (mt == 1) ? g_yk : g_yv;
    } else {
        mt = 3;
        Bhi = g_bqhi; Blo = g_bqlo;
        out = g_yq;
    }
    const uint32_t* Ahi = g_wpkhi[mt];
    const uint32_t* Alo = g_wpklo[mt];
    int m0 = blockIdx.y * BM;
    int yoff = blockIdx.y * 8;
    int n0 = blockIdx.x * BN;
    int tid = threadIdx.x;
    int lane = tid & 31, wid = tid >> 5;
    int wm = wid >> 2;
    int wn = wid & 3;

    size_t bfrag;
    {
        int nf = tid >> 5, g2 = (tid & 31) >> 2, cc = tid & 3;
        bfrag = (size_t)(n0 + nf * 8 + g2) * 8 + cc * 2;
    }

    float acc1[4][2][4], acc2[4][2][4];
#pragma unroll
    for (int i = 0; i < 4; i++)
#pragma unroll
        for (int j = 0; j < 2; j++)
#pragma unroll
            for (int r = 0; r < 4; r++) { acc1[i][j][r] = 0.f; acc2[i][j][r] = 0.f; }

    stage_cp(smb, Ahi, Alo, Bhi, Blo, bfrag, 0, yoff, tid);
    CP_COMMIT();
    CP_WAIT0();
    __syncthreads();

    for (int kc = 0; kc < C_DIM / BK; kc++) {
        uint32_t* sb = sm32 + (kc & 1) * BUF_WORDS;
        bool more = (kc + 1 < C_DIM / BK);
        if (more) {
            stage_cp(smb + ((kc + 1) & 1) * BUF_WORDS * 4, Ahi, Alo, Bhi, Blo, bfrag, kc + 1, yoff, tid);
            CP_COMMIT();
        }

#pragma unroll
        for (int kf = 0; kf < 2; kf++) {
            uint32_t Bh[2][2], Bl[2][2];
#pragma unroll
            for (int j = 0; j < 2; j++) {
                int fi = kf * 512 + ((wn * 2 + j) * 32 + lane) * 2;
                uint2 bh = *reinterpret_cast<const uint2*>(sb + BH_OFF + fi);
                uint2 bl = *reinterpret_cast<const uint2*>(sb + BL_OFF + fi);
                Bh[j][0] = bh.x; Bh[j][1] = bh.y;
                Bl[j][0] = bl.x; Bl[j][1] = bl.y;
            }
#pragma unroll
            for (int i = 0; i < 4; i++) {
                int fi = kf * 1024 + ((wm * 4 + i) * 32 + lane) * 4;
                uint4 a4 = *reinterpret_cast<const uint4*>(sb + AH_OFF + fi);
                uint4 l4 = *reinterpret_cast<const uint4*>(sb + AL_OFF + fi);
                uint32_t Ah[4] = {a4.x, a4.y, a4.z, a4.w};
                uint32_t Al[4] = {l4.x, l4.y, l4.z, l4.w};
#pragma unroll
                for (int j = 0; j < 2; j++) {
                    mma16(acc1[i][j], Ah, Bh[j]);
                    mma16(acc2[i][j], Ah, Bl[j]);
                    mma16(acc2[i][j], Al, Bh[j]);
                }
            }
        }
        if (more) CP_WAIT0();
        __syncthreads();
    }

    int g = lane >> 2, c = lane & 3;
#pragma unroll
    for (int i = 0; i < 4; i++) {
        int r0 = m0 + wm * 64 + i * 16 + g;
        int r1 = r0 + 8;
        float sc0 = g_scale[mt][r0], sh0 = g_shift[mt][r0];
        float sc1 = g_scale[mt][r1], sh1 = g_shift[mt][r1];
#pragma unroll
        for (int j = 0; j < 2; j++) {
            int ncol = n0 + (wn * 2 + j) * 8 + c * 2;
            float v0 = acc1[i][j][0] + acc2[i][j][0] * LO_INV;
            float v1 = acc1[i][j][1] + acc2[i][j][1] * LO_INV;
            float v2 = acc1[i][j][2] + acc2[i][j][2] * LO_INV;
            float v3 = acc1[i][j][3] + acc2[i][j][3] * LO_INV;
            *reinterpret_cast<float2*>(out + (size_t)r0 * NF + ncol) =
                make_float2(v0 * sc0 + sh0, v1 * sc0 + sh0);
            *reinterpret_cast<float2*>(out + (size_t)r1 * NF + ncol) =
                make_float2(v2 * sc1 + sh1, v3 * sc1 + sh1);
        }
    }
}

// ---------------- K3: triple LIF + kv_local (u8 spikes, 2 chains/thread) ----------------
__global__ void k_lif3() {
    int gid = blockIdx.x * 256 + threadIdx.x;
    if (gid >= PLANE / 2) return;
    int e0 = gid, e1 = gid + PLANE / 2;
    int c0 = e0 / 800, c1 = e1 / 800;
    int b0 = c0 * NF + (e0 - c0 * 800);
    int b1 = c1 * NF + (e1 - c1 * 800);
    float vq0 = 0.f, vk0 = 0.f, vv0 = 0.f;
    float vq1 = 0.f, vk1 = 0.f, vv1 = 0.f;
    for (int t = 0; t < T_DIM; t++) {
        int o0 = b0 + t * 800, o1 = b1 + t * 800;
        float aq0 = __ldcs(g_yq + o0), aq1 = __ldcs(g_yq + o1);
        float ak0 = __ldcs(g_yk + o0), ak1 = __ldcs(g_yk + o1);
        float av0 = __ldcs(g_yv + o0), av1 = __ldcs(g_yv + o1);
        float q0 = vq0 + (aq0 - vq0) * 0.5f;
        float sq0 = (q0 >= 1.f) ? 1.f : 0.f;
        vq0 = q0 * (1.f - sq0);
        float k0 = vk0 + (ak0 - vk0) * 0.5f;
        float sk0 = (k0 >= 1.f) ? 1.f : 0.f;
        vk0 = k0 * (1.f - sk0);
        float v0 = vv0 + (av0 - vv0) * 0.5f;
        float sv0 = (v0 >= 1.f) ? 1.f : 0.f;
        vv0 = v0 * (1.f - sv0);
        float q1 = vq1 + (aq1 - vq1) * 0.5f;
        float sq1 = (q1 >= 1.f) ? 1.f : 0.f;
        vq1 = q1 * (1.f - sq1);
        float k1 = vk1 + (ak1 - vk1) * 0.5f;
        float sk1 = (k1 >= 1.f) ? 1.f : 0.f;
        vk1 = k1 * (1.f - sk1);
        float v1 = vv1 + (av1 - vv1) * 0.5f;
        float sv1 = (v1 >= 1.f) ? 1.f : 0.f;
        vv1 = v1 * (1.f - sv1);
        g_qs8[o0] = (unsigned char)sq0;
        g_qs8[o1] = (unsigned char)sq1;
        g_kvl8[o0] = (unsigned char)(sk0 * sv0);
        g_kvl8[o1] = (unsigned char)(sk1 * sv1);
    }
}

// ---------------- K4: topo routing + LIF(0.5) + SSRE -> packed attn ----------------
__global__ void __launch_bounds__(224) k_topo_ssre() {
    int bid = blockIdx.x;
    int b = bid >> 5;
    int rest = bid & 31;
    int h = rest >> 2;
    int dg = rest & 3;
    int tid = threadIdx.x;

    __shared__ float topo_s[V_DIM * V_DIM];
    __shared__ float kvb[2][200];
    __shared__ float satt[200];
    for (int i = tid; i < V_DIM * V_DIM; i += 224) topo_s[i] = g_topo[h][i];

    bool active = tid < 200;
    int d_local = tid / V_DIM;
    int i = tid - d_local * V_DIM;
    int c = h * HD_DIM + dg * 8 + d_local;
    int pbase = c * NF + b * V_DIM + i;
    int cb = h * HD_DIM + dg * 8;

    bool packer = tid < 100;
    int pp = 0, pi = 0;
    size_t paddr_base = 0;
    if (packer) {
        int p = tid / V_DIM;
        pi = tid - p * V_DIM;
        int pj = (cb >> 1) + p;
        int K = pj >> 3;
        int c2w = ((pj & 3) << 1) | ((pj >> 2) & 1);
        paddr_base = ((size_t)K * NF + b * V_DIM + pi) * 8 + c2w;
        pp = p;
    }

    float dec = 0.f;
    if (active) dec = g_decay[h * HD_DIM + dg * 8 + d_local];
    float omd = 1.f - dec;
    float vm = 0.f, S = 0.f;

    if (active) kvb[0][tid] = (float)g_kvl8[pbase];

    for (int t = 0; t < T_DIM; t++) {
        __syncthreads();
        int cur = t & 1;
        if (t + 1 < T_DIM && active) kvb[cur ^ 1][tid] = (float)g_kvl8[pbase + (t + 1) * 800];
        if (active) {
            const float* kr = &kvb[cur][d_local * V_DIM];
            const float* tr = &topo_s[i * V_DIM];
            float sp = 0.f, sp2 = 0.f;
#pragma unroll
            for (int j = 0; j < 24; j += 2) {
                sp += tr[j] * kr[j];
                sp2 += tr[j + 1] * kr[j + 1];
            }
            sp += tr[24] * kr[24] + sp2;
            vm = vm + (sp - vm) * 0.5f;
            float sk = (vm >= 0.5f) ? 1.f : 0.f;
            vm *= (1.f - sk);
            S = dec * S + omd * sk;
            satt[tid] = g_qs8[pbase + t * 800] ? S : 0.f;
        }
        __syncthreads();
        if (packer) {
            float f0 = satt[(2 * pp) * V_DIM + pi];
            float f1 = satt[(2 * pp + 1) * V_DIM + pi];
            uint32_t hw, lw;
            split_h2(f0, f1, hw, lw);
            size_t addr = paddr_base + (size_t)t * (800 * 8);
            g_bqhi[addr] = hw;
            g_bqlo[addr] = lw;
        }
    }
}

// ---------------- K6: final LIF(0.5) + identity (2 chains/thread) ----------------
__global__ void k_final(const float* __restrict__ x, float* __restrict__ out) {
    int gid = blockIdx.x * 256 + threadIdx.x;
    if (gid >= PLANE / 2) return;
    int e0 = gid, e1 = gid + PLANE / 2;
    int c0 = e0 / 800, c1 = e1 / 800;
    int nb0 = e0 - c0 * 800, nb1 = e1 - c1 * 800;
    int bb0 = nb0 / V_DIM, bb1 = nb1 / V_DIM;
    int v0 = nb0 - bb0 * V_DIM, v1 = nb1 - bb1 * V_DIM;
    int y0 = c0 * NF + nb0, y1 = c1 * NF + nb1;
    int x0 = bb0 * (C_DIM * V_DIM) + c0 * V_DIM + v0;
    int x1 = bb1 * (C_DIM * V_DIM) + c1 * V_DIM + v1;
    float vm0 = 0.f, vm1 = 0.f;
    for (int t = 0; t < T_DIM; t++) {
        float ya = __ldcs(g_yq + y0 + t * 800);
        float yb = __ldcs(g_yq + y1 + t * 800);
        float a0 = vm0 + (ya - vm0) * 0.5f;
        float s0 = (a0 >= 0.5f) ? 1.f : 0.f;
        vm0 = a0 * (1.f - s0);
        float a1 = vm1 + (yb - vm1) * 0.5f;
        float s1 = (a1 >= 0.5f) ? 1.f : 0.f;
        vm1 = a1 * (1.f - s1);
        int xo0 = t * PLANE + x0, xo1 = t * PLANE + x1;
        out[xo0] = s0 + x[xo0];
        out[xo1] = s1 + x[xo1];
    }
}

// ---------------- launch ----------------
extern "C" void kernel_launch(void* const* d_in, const int* in_sizes, int n_in,
                              void* d_out, int out_size) {
    const float* x = (const float*)d_in[0];
    const float* alpha = (const float*)d_in[1];

    PrepArgs p;
    p.w[0] = (const float*)d_in[2];
    p.w[1] = (const float*)d_in[3];
    p.w[2] = (const float*)d_in[4];

    if (in_sizes[5] == 625) {
        p.base    = (const float*)d_in[5];
        p.learned = (const float*)d_in[6];
        p.sdw     = (const float*)d_in[7];
        p.w[3]    = (const float*)d_in[8];
        p.projb   = (const float*)d_in[9];
        for (int m = 0; m < 4; m++) {
            int o = 10 + m * 4;
            p.gamma[m] = (const float*)d_in[o + 0];
            p.beta[m]  = (const float*)d_in[o + 1];
            p.mean[m]  = (const float*)d_in[o + 2];
            p.var[m]   = (const float*)d_in[o + 3];
        }
    } else {
        for (int m = 0; m < 3; m++) {
            int o = 5 + m * 4;
            p.gamma[m] = (const float*)d_in[o + 0];
            p.beta[m]  = (const float*)d_in[o + 1];
            p.mean[m]  = (const float*)d_in[o + 2];
            p.var[m]   = (const float*)d_in[o + 3];
        }
        p.base    = (const float*)d_in[17];
        p.learned = (const float*)d_in[18];
        p.sdw     = (const float*)d_in[19];
        p.w[3]    = (const float*)d_in[20];
        p.projb   = (const float*)d_in[21];
        p.gamma[3] = (const float*)d_in[22];
        p.beta[3]  = (const float*)d_in[23];
        p.mean[3]  = (const float*)d_in[24];
        p.var[3]   = (const float*)d_in[25];
    }

    float* out = (float*)d_out;

    cudaFuncSetAttribute(k_gemm_mma, cudaFuncAttributeMaxDynamicSharedMemorySize, GSMEM_BYTES);
    int tsm = 2 * C_DIM * V_DIM * 4;   // 51200 B
    cudaFuncSetAttribute(k_trans, cudaFuncAttributeMaxDynamicSharedMemorySize, tsm);

    k_prep<<<6, 256>>>(p);
    k_trans<<<T_DIM * B_DIM, 256, tsm>>>(x, alpha);
    k_gemm_mma<<<dim3(NF / BN, 2, 3), GTHREADS, GSMEM_BYTES>>>(0);
    k_lif3<<<(PLANE / 2 + 255) / 256, 256>>>();
    k_topo_ssre<<<B_DIM * H_DIM * 4, 224>>>();
    k_gemm_mma<<<dim3(NF / BN, 2, 1), GTHREADS, GSMEM_BYTES>>>(1);
    k_final<<<(PLANE / 2 + 255) / 256, 256>>>(x, out);
}

// round 17
// speedup vs baseline: 1.0935x; 1.0414x over previous
#include <cuda_runtime.h>
#include <cuda_fp16.h>
#include <math.h>
#include <stdint.h>

typedef unsigned long long ull;

// ---------------- problem constants ----------------
#define T_DIM 64
#define B_DIM 32
#define C_DIM 256
#define V_DIM 25
#define H_DIM 8
#define HD_DIM 32
#define PLANE  (B_DIM * C_DIM * V_DIM)    // 204800
#define TOT    (T_DIM * PLANE)            // 13107200
#define NF     (T_DIM * B_DIM * V_DIM)    // 51200  (GEMM N)
#define BWORDS ((size_t)16 * NF * 8)      // words per B plane

// ---------------- device scratch ----------------
__device__ __align__(16) float g_yq[TOT];    // q bn-conv out; later proj bn-conv out
__device__ __align__(16) float g_yk[TOT];
__device__ __align__(16) float g_yv[TOT];
__device__ unsigned char g_qs8[TOT];         // q spikes (0/1)
__device__ unsigned char g_kvl8[TOT];        // k_s * v_s (0/1)

// pre-packed weight fragments: [k16 0..15][mf 0..15][lane 0..31][w 0..3]
__device__ __align__(16) uint32_t g_wpkhi[4][32768];
__device__ __align__(16) uint32_t g_wpklo[4][32768];

// pre-packed B fragment planes
__device__ __align__(16) uint32_t g_bxhi[BWORDS];
__device__ __align__(16) uint32_t g_bxlo[BWORDS];
__device__ __align__(16) uint32_t g_bqhi[BWORDS];   // qkv_in; later attn
__device__ __align__(16) uint32_t g_bqlo[BWORDS];

__device__ float g_scale[4][C_DIM];
__device__ float g_shift[4][C_DIM];
__device__ float g_topo[H_DIM][V_DIM * V_DIM];
__device__ float g_decay[C_DIM];

// ---------------- helpers ----------------
#define LO_SCALE 1024.0f
#define LO_INV   (1.0f / 1024.0f)

__device__ __forceinline__ void split_h2(float a, float b, uint32_t& h, uint32_t& l) {
    __half ha = __float2half_rn(a), hb = __float2half_rn(b);
    float ra = (a - __half2float(ha)) * LO_SCALE;
    float rb = (b - __half2float(hb)) * LO_SCALE;
    __half la = __float2half_rn(ra), lb = __float2half_rn(rb);
    __half2 hh = __halves2half2(ha, hb), ll = __halves2half2(la, lb);
    h = *reinterpret_cast<uint32_t*>(&hh);
    l = *reinterpret_cast<uint32_t*>(&ll);
}

__device__ __forceinline__ void mma16(float* c, const uint32_t* a, const uint32_t* b) {
    asm volatile(
        "mma.sync.aligned.m16n8k16.row.col.f32.f16.f16.f32 "
        "{%0,%1,%2,%3}, {%4,%5,%6,%7}, {%8,%9}, {%0,%1,%2,%3};"
        : "+f"(c[0]), "+f"(c[1]), "+f"(c[2]), "+f"(c[3])
        : "r"(a[0]), "r"(a[1]), "r"(a[2]), "r"(a[3]), "r"(b[0]), "r"(b[1]));
}

__device__ __forceinline__ void cp16(uint32_t saddr, const void* g) {
    asm volatile("cp.async.ca.shared.global [%0], [%1], 16;" :: "r"(saddr), "l"(g) : "memory");
}
__device__ __forceinline__ void cp8(uint32_t saddr, const void* g) {
    asm volatile("cp.async.ca.shared.global [%0], [%1], 8;" :: "r"(saddr), "l"(g) : "memory");
}
#define CP_COMMIT() asm volatile("cp.async.commit_group;" ::: "memory")
#define CP_WAIT0()  asm volatile("cp.async.wait_group 0;" ::: "memory")
#define CP_WAIT1()  asm volatile("cp.async.wait_group 1;" ::: "memory")

// ---------------- K0: prep ----------------
struct PrepArgs {
    const float* w[4];
    const float* gamma[4];
    const float* beta[4];
    const float* mean[4];
    const float* var[4];
    const float* projb;
    const float* base;
    const float* learned;
    const float* sdw;
};

__global__ void k_prep(PrepArgs p) {
    int blk = blockIdx.x, tid = threadIdx.x;
    if (blk < 4) {
        const float* w = p.w[blk];
        for (int idx = tid; idx < 32768; idx += 256) {
            int k16 = idx >> 11;
            int rest = idx & 2047;
            int mf = rest >> 7;
            int r2 = rest & 127;
            int lane = r2 >> 2;
            int wq = r2 & 3;
            int g = lane >> 2, c = lane & 3;
            int row = mf * 16 + g + (wq & 1) * 8;
            int col = k16 * 16 + 2 * c + ((wq & 2) ? 8 : 0);
            uint32_t hi, lo;
            split_h2(w[row * C_DIM + col], w[row * C_DIM + col + 1], hi, lo);
            g_wpkhi[blk][idx] = hi;
            g_wpklo[blk][idx] = lo;
        }
        float sc = p.gamma[blk][tid] * rsqrtf(p.var[blk][tid] + 1e-5f);
        float sh = p.beta[blk][tid] - p.mean[blk][tid] * sc;
        if (blk == 3) sh += p.projb[tid] * sc;
        g_scale[blk][tid] = sc;
        g_shift[blk][tid] = sh;
    } else if (blk == 4) {
        if (tid < H_DIM * V_DIM) {
            int h = tid / V_DIM, i = tid - h * V_DIM;
            float l[V_DIM];
            float mx = -1e30f;
            for (int j = 0; j < V_DIM; j++) {
                l[j] = p.base[i * V_DIM + j] + 0.5f * p.learned[(h * V_DIM + i) * V_DIM + j];
                mx = fmaxf(mx, l[j]);
            }
            float sum = 0.f;
            for (int j = 0; j < V_DIM; j++) { l[j] = expf(l[j] - mx); sum += l[j]; }
            float inv = 1.f / sum;
            for (int j = 0; j < V_DIM; j++) g_topo[h][i * V_DIM + j] = l[j] * inv;
        }
    } else {
        float w = p.sdw[tid];
        float sg = 1.f / (1.f + expf(-w));
        g_decay[tid] = fminf(0.99f, fmaxf(0.01f, sg));
    }
}

// ---------------- K1: transpose + split-pack x and qkv_in ----------------
__global__ void k_trans(const float* __restrict__ x, const float* __restrict__ alpha) {
    extern __shared__ float dynsm[];
    float* sxf = dynsm;
    float* sqf = dynsm + C_DIM * V_DIM;
    __shared__ float alp[C_DIM];
    int tid = threadIdx.x;
    alp[tid] = alpha[tid];
    __syncthreads();

    int t = blockIdx.x >> 5;
    int b = blockIdx.x & 31;
    const float* xin = x + (size_t)t * PLANE + b * (C_DIM * V_DIM);
    const float* xpr = xin - PLANE;
    int nbase = t * 800 + b * V_DIM;

    for (int idx = tid; idx < C_DIM * V_DIM; idx += 256) {
        int c = idx / V_DIM;
        float xv = xin[idx];
        float g = (t == 0) ? 0.f : fabsf(xv - xpr[idx]);
        float a = alp[c];
        sxf[idx] = xv;
        sqf[idx] = a * g + (1.f - a) * xv;
    }
    __syncthreads();

    for (int widx = tid; widx < V_DIM * 128; widx += 256) {
        int v = widx >> 7, j = widx & 127;
        int base = 2 * j * V_DIM + v;
        int K = j >> 3;
        int c2w = ((j & 3) << 1) | ((j >> 2) & 1);
        size_t addr = ((size_t)K * NF + (nbase + v)) * 8 + c2w;
        uint32_t h, l;
        split_h2(sxf[base], sxf[base + V_DIM], h, l);
        g_bxhi[addr] = h; g_bxlo[addr] = l;
        split_h2(sqf[base], sqf[base + V_DIM], h, l);
        g_bqhi[addr] = h; g_bqlo[addr] = l;
    }
}

// ---------------- K2/K5: fp16x3 mma.sync GEMM + fused BN (3-stage cp.async) ----------------
// Block tile 128x64, BK=32, 256 threads (8 warps), warp tile 64x16, 2 CTA/SM.
#define BM 128
#define BN 64
#define BK 32
#define GTHREADS 256
#define AH_OFF 0
#define AL_OFF 2048
#define BH_OFF 4096
#define BL_OFF 5120
#define BUF_WORDS 6144
#define NSTAGE 3
#define GSMEM_BYTES (NSTAGE * BUF_WORDS * 4)
#define NCHUNK (C_DIM / BK)

__device__ __forceinline__ void stage_cp(uint32_t smb,
                                         const uint32_t* __restrict__ Ahi, const uint32_t* __restrict__ Alo,
                                         const uint32_t* __restrict__ Bhi, const uint32_t* __restrict__ Blo,
                                         size_t bfrag, int kc, int yoff, int tid) {
#pragma unroll
    for (int kf = 0; kf < 2; kf++) {
        size_t abase = ((size_t)((kc * 2 + kf) * 16 + yoff + (tid >> 5)) << 7) + (tid & 31) * 4;
        cp16(smb + (AH_OFF + kf * 1024 + tid * 4) * 4, Ahi + abase);
        cp16(smb + (AL_OFF + kf * 1024 + tid * 4) * 4, Alo + abase);
        size_t baddr = (size_t)(kc * 2 + kf) * (NF * 8) + bfrag;
        cp8(smb + (BH_OFF + kf * 512 + tid * 2) * 4, Bhi + baddr);
        cp8(smb + (BL_OFF + kf * 512 + tid * 2) * 4, Blo + baddr);
    }
}

__global__ void __launch_bounds__(GTHREADS, 2) k_gemm_mma(int pass) {
    extern __shared__ uint32_t sm32[];
    uint32_t smb = (uint32_t)__cvta_generic_to_shared(sm32);
    int mt;
    const uint32_t* Bhi;
    const uint32_t* Blo;
    float* out;
    if (pass == 0) {
        mt = blockIdx.z;
        if (mt == 2) { Bhi = g_bxhi; Blo = g_bxlo; }
        else         { Bhi = g_bqhi; Blo = g_bqlo; }
        out = (mt == 0) ? g_yq : (mt == 1) ? g_yk : g_yv;
    } else {
        mt = 3;
        Bhi = g_bqhi; Blo = g_bqlo;
        out = g_yq;
    }
    const uint32_t* Ahi = g_wpkhi[mt];
    const uint32_t* Alo = g_wpklo[mt];
    int m0 = blockIdx.y * BM;
    int yoff = blockIdx.y * 8;
    int n0 = blockIdx.x * BN;
    int tid = threadIdx.x;
    int lane = tid & 31, wid = tid >> 5;
    int wm = wid >> 2;
    int wn = wid & 3;

    size_t bfrag;
    {
        int nf = tid >> 5, g2 = (tid & 31) >> 2, cc = tid & 3;
        bfrag = (size_t)(n0 + nf * 8 + g2) * 8 + cc * 2;
    }

    float acc1[4][2][4], acc2[4][2][4];
#pragma unroll
    for (int i = 0; i < 4; i++)
#pragma unroll
        for (int j = 0; j < 2; j++)
#pragma unroll
            for (int r = 0; r < 4; r++) { acc1[i][j][r] = 0.f; acc2[i][j][r] = 0.f; }

    // prologue: prefetch chunks 0 and 1
    stage_cp(smb, Ahi, Alo, Bhi, Blo, bfrag, 0, yoff, tid);
    CP_COMMIT();
    stage_cp(smb + BUF_WORDS * 4, Ahi, Alo, Bhi, Blo, bfrag, 1, yoff, tid);
    CP_COMMIT();
    CP_WAIT1();           // chunk 0 complete
    __syncthreads();

    int bufidx = 0;
    for (int kc = 0; kc < NCHUNK; kc++) {
        uint32_t* sb = sm32 + bufidx * BUF_WORDS;
        if (kc + 2 < NCHUNK) {
            int nb = bufidx + 2;
            if (nb >= NSTAGE) nb -= NSTAGE;
            stage_cp(smb + nb * BUF_WORDS * 4, Ahi, Alo, Bhi, Blo, bfrag, kc + 2, yoff, tid);
            CP_COMMIT();
        }

#pragma unroll
        for (int kf = 0; kf < 2; kf++) {
            uint32_t Bh[2][2], Bl[2][2];
#pragma unroll
            for (int j = 0; j < 2; j++) {
                int fi = kf * 512 + ((wn * 2 + j) * 32 + lane) * 2;
                uint2 bh = *reinterpret_cast<const uint2*>(sb + BH_OFF + fi);
                uint2 bl = *reinterpret_cast<const uint2*>(sb + BL_OFF + fi);
                Bh[j][0] = bh.x; Bh[j][1] = bh.y;
                Bl[j][0] = bl.x; Bl[j][1] = bl.y;
            }
#pragma unroll
            for (int i = 0; i < 4; i++) {
                int fi = kf * 1024 + ((wm * 4 + i) * 32 + lane) * 4;
                uint4 a4 = *reinterpret_cast<const uint4*>(sb + AH_OFF + fi);
                uint4 l4 = *reinterpret_cast<const uint4*>(sb + AL_OFF + fi);
                uint32_t Ah[4] = {a4.x, a4.y, a4.z, a4.w};
                uint32_t Al[4] = {l4.x, l4.y, l4.z, l4.w};
#pragma unroll
                for (int j = 0; j < 2; j++) {
                    mma16(acc1[i][j], Ah, Bh[j]);
                    mma16(acc2[i][j], Ah, Bl[j]);
                    mma16(acc2[i][j], Al, Bh[j]);
                }
            }
        }
        if (kc + 1 < NCHUNK) {
            if (kc + 2 < NCHUNK) CP_WAIT1(); else CP_WAIT0();
            __syncthreads();
        }
        bufidx++;
        if (bufidx >= NSTAGE) bufidx = 0;
    }

    int g = lane >> 2, c = lane & 3;
#pragma unroll
    for (int i = 0; i < 4; i++) {
        int r0 = m0 + wm * 64 + i * 16 + g;
        int r1 = r0 + 8;
        float sc0 = g_scale[mt][r0], sh0 = g_shift[mt][r0];
        float sc1 = g_scale[mt][r1], sh1 = g_shift[mt][r1];
#pragma unroll
        for (int j = 0; j < 2; j++) {
            int ncol = n0 + (wn * 2 + j) * 8 + c * 2;
            float v0 = acc1[i][j][0] + acc2[i][j][0] * LO_INV;
            float v1 = acc1[i][j][1] + acc2[i][j][1] * LO_INV;
            float v2 = acc1[i][j][2] + acc2[i][j][2] * LO_INV;
            float v3 = acc1[i][j][3] + acc2[i][j][3] * LO_INV;
            *reinterpret_cast<float2*>(out + (size_t)r0 * NF + ncol) =
                make_float2(v0 * sc0 + sh0, v1 * sc0 + sh0);
            *reinterpret_cast<float2*>(out + (size_t)r1 * NF + ncol) =
                make_float2(v2 * sc1 + sh1, v3 * sc1 + sh1);
        }
    }
}

// ---------------- K3: triple LIF + kv_local (u8 spikes) ----------------
__global__ void k_lif3() {
    int e = blockIdx.x * 256 + threadIdx.x;
    if (e >= PLANE) return;
    int c = e / 800;
    int nb = e - c * 800;
    int bse = c * NF + nb;
    float vq = 0.f, vk = 0.f, vv = 0.f;
    for (int t = 0; t < T_DIM; t++) {
        int off = bse + t * 800;
        float aq = __ldcs(g_yq + off);
        float ak = __ldcs(g_yk + off);
        float av = __ldcs(g_yv + off);
        float q = vq + (aq - vq) * 0.5f;
        float sq = (q >= 1.f) ? 1.f : 0.f;
        vq = q * (1.f - sq);
        float k = vk + (ak - vk) * 0.5f;
        float sk = (k >= 1.f) ? 1.f : 0.f;
        vk = k * (1.f - sk);
        float v = vv + (av - vv) * 0.5f;
        float sv = (v >= 1.f) ? 1.f : 0.f;
        vv = v * (1.f - sv);
        g_qs8[off] = (unsigned char)sq;
        g_kvl8[off] = (unsigned char)(sk * sv);
    }
}

// ---------------- K4: topo routing + LIF(0.5) + SSRE -> packed attn ----------------
__global__ void __launch_bounds__(224) k_topo_ssre() {
    int bid = blockIdx.x;
    int b = bid >> 5;
    int rest = bid & 31;
    int h = rest >> 2;
    int dg = rest & 3;
    int tid = threadIdx.x;

    __shared__ float topo_s[V_DIM * V_DIM];
    __shared__ float kvb[2][200];
    __shared__ float satt[200];
    for (int i = tid; i < V_DIM * V_DIM; i += 224) topo_s[i] = g_topo[h][i];

    bool active = tid < 200;
    int d_local = tid / V_DIM;
    int i = tid - d_local * V_DIM;
    int c = h * HD_DIM + dg * 8 + d_local;
    int pbase = c * NF + b * V_DIM + i;
    int cb = h * HD_DIM + dg * 8;

    bool packer = tid < 100;
    int pp = 0, pi = 0;
    size_t paddr_base = 0;
    if (packer) {
        int p = tid / V_DIM;
        pi = tid - p * V_DIM;
        int pj = (cb >> 1) + p;
        int K = pj >> 3;
        int c2w = ((pj & 3) << 1) | ((pj >> 2) & 1);
        paddr_base = ((size_t)K * NF + b * V_DIM + pi) * 8 + c2w;
        pp = p;
    }

    float dec = 0.f;
    if (active) dec = g_decay[h * HD_DIM + dg * 8 + d_local];
    float omd = 1.f - dec;
    float vm = 0.f, S = 0.f;

    if (active) kvb[0][tid] = (float)g_kvl8[pbase];

    for (int t = 0; t < T_DIM; t++) {
        __syncthreads();
        int cur = t & 1;
        if (t + 1 < T_DIM && active) kvb[cur ^ 1][tid] = (float)g_kvl8[pbase + (t + 1) * 800];
        if (active) {
            const float* kr = &kvb[cur][d_local * V_DIM];
            const float* tr = &topo_s[i * V_DIM];
            float sp = 0.f, sp2 = 0.f;
#pragma unroll
            for (int j = 0; j < 24; j += 2) {
                sp += tr[j] * kr[j];
                sp2 += tr[j + 1] * kr[j + 1];
            }
            sp += tr[24] * kr[24] + sp2;
            vm = vm + (sp - vm) * 0.5f;
            float sk = (vm >= 0.5f) ? 1.f : 0.f;
            vm *= (1.f - sk);
            S = dec * S + omd * sk;
            satt[tid] = g_qs8[pbase + t * 800] ? S : 0.f;
        }
        __syncthreads();
        if (packer) {
            float f0 = satt[(2 * pp) * V_DIM + pi];
            float f1 = satt[(2 * pp + 1) * V_DIM + pi];
            uint32_t hw, lw;
            split_h2(f0, f1, hw, lw);
            size_t addr = paddr_base + (size_t)t * (800 * 8);
            g_bqhi[addr] = hw;
            g_bqlo[addr] = lw;
        }
    }
}

// ---------------- K6: final LIF(0.5) + identity ----------------
__global__ void k_final(const float* __restrict__ x, float* __restrict__ out) {
    int e = blockIdx.x * 256 + threadIdx.x;
    if (e >= PLANE) return;
    int c = e / 800;
    int nb = e - c * 800;
    int b = nb / V_DIM;
    int v = nb - b * V_DIM;
    int ybase = c * NF + nb;
    int xoff = b * (C_DIM * V_DIM) + c * V_DIM + v;
    float vm = 0.f;
    for (int t = 0; t < T_DIM; t++) {
        float y = __ldcs(g_yq + ybase + t * 800);
        float vv = vm + (y - vm) * 0.5f;
        float s = (vv >= 0.5f) ? 1.f : 0.f;
        vm = vv * (1.f - s);
        int xo = t * PLANE + xoff;
        out[xo] = s + x[xo];
    }
}

// ---------------- launch ----------------
extern "C" void kernel_launch(void* const* d_in, const int* in_sizes, int n_in,
                              void* d_out, int out_size) {
    const float* x = (const float*)d_in[0];
    const float* alpha = (const float*)d_in[1];

    PrepArgs p;
    p.w[0] = (const float*)d_in[2];
    p.w[1] = (const float*)d_in[3];
    p.w[2] = (const float*)d_in[4];

    if (in_sizes[5] == 625) {
        p.base    = (const float*)d_in[5];
        p.learned = (const float*)d_in[6];
        p.sdw     = (const float*)d_in[7];
        p.w[3]    = (const float*)d_in[8];
        p.projb   = (const float*)d_in[9];
        for (int m = 0; m < 4; m++) {
            int o = 10 + m * 4;
            p.gamma[m] = (const float*)d_in[o + 0];
            p.beta[m]  = (const float*)d_in[o + 1];
            p.mean[m]  = (const float*)d_in[o + 2];
            p.var[m]   = (const float*)d_in[o + 3];
        }
    } else {
        for (int m = 0; m < 3; m++) {
            int o = 5 + m * 4;
            p.gamma[m] = (const float*)d_in[o + 0];
            p.beta[m]  = (const float*)d_in[o + 1];
            p.mean[m]  = (const float*)d_in[o + 2];
            p.var[m]   = (const float*)d_in[o + 3];
        }
        p.base    = (const float*)d_in[17];
        p.learned = (const float*)d_in[18];
        p.sdw     = (const float*)d_in[19];
        p.w[3]    = (const float*)d_in[20];
        p.projb   = (const float*)d_in[21];
        p.gamma[3] = (const float*)d_in[22];
        p.beta[3]  = (const float*)d_in[23];
        p.mean[3]  = (const float*)d_in[24];
        p.var[3]   = (const float*)d_in[25];
    }

    float* out = (float*)d_out;

    cudaFuncSetAttribute(k_gemm_mma, cudaFuncAttributeMaxDynamicSharedMemorySize, GSMEM_BYTES);
    int tsm = 2 * C_DIM * V_DIM * 4;   // 51200 B
    cudaFuncSetAttribute(k_trans, cudaFuncAttributeMaxDynamicSharedMemorySize, tsm);

    k_prep<<<6, 256>>>(p);
    k_trans<<<T_DIM * B_DIM, 256, tsm>>>(x, alpha);
    k_gemm_mma<<<dim3(NF / BN, 2, 3), GTHREADS, GSMEM_BYTES>>>(0);
    k_lif3<<<(PLANE + 255) / 256, 256>>>();
    k_topo_ssre<<<B_DIM * H_DIM * 4, 224>>>();
    k_gemm_mma<<<dim3(NF / BN, 2, 1), GTHREADS, GSMEM_BYTES>>>(1);
    k_final<<<(PLANE + 255) / 256, 256>>>(x, out);
}